// round 16
// baseline (speedup 1.0000x reference)
#include <cuda_runtime.h>
#include <cuda_bf16.h>
#include <cstdint>

// Locally-connected conv via mma.sync bf16 split precision.
// CTA = 512 threads = 2 position-groups (w0, w0+1) x 8 warps.
// Split-K x2: warp (m, kh) handles output rows m*16..+16, k stages (2s+kh)*16.
// Warp-private cp.async rings, 5 deep, prefetch distance 4, zero main-loop barriers.
// Epilogue: kh=1 partial sums exchanged via smem (stride-33), kh=0 adds+stores.
// Out = WhXh + WhXl + WlXh (+bias); dropped WlXl ~ 2^-17.

#define B_    32
#define CIN_  32
#define IH_   64
#define IW_   64
#define COUT_ 64
#define OH_   64
#define OW_   64
#define KTOT  288
#define KROW  296               // X tile row stride (bf16) = 592 B
#define NSTW  9                 // k16 stages per warp (split-K x2)
#define SROW  20                // ring row stride (floats) = 80 B, LDS conflict-free
#define WSTG  (16 * SROW * 4)   // 1280 B per warp-stage
#define NBUF  5

#define XS_BYTES (64 * KROW * 2)            // 37888 per group
#define RING_BYTES (NBUF * WSTG)            // 6400 per warp
#define SMEM_DYN (2 * XS_BYTES + 16 * RING_BYTES)   // 178176 -> 1 CTA/SM, 16 warps

__device__ __forceinline__ uint32_t prmt_hi(uint32_t a, uint32_t b) {
    uint32_t r; asm("prmt.b32 %0, %1, %2, 0x7632;" : "=r"(r) : "r"(a), "r"(b)); return r;
}
__device__ __forceinline__ uint32_t lo_pack2(float fx, float fy) {
    float h0 = __uint_as_float(__float_as_uint(fx) & 0xFFFF0000u);
    float h1 = __uint_as_float(__float_as_uint(fy) & 0xFFFF0000u);
    __nv_bfloat162 p = __floats2bfloat162_rn(fx - h0, fy - h1);
    return reinterpret_cast<uint32_t&>(p);
}
__device__ __forceinline__ void ldsm4(uint32_t& r0, uint32_t& r1, uint32_t& r2, uint32_t& r3,
                                      uint32_t a) {
    asm volatile("ldmatrix.sync.aligned.m8n8.x4.shared.b16 {%0,%1,%2,%3}, [%4];"
                 : "=r"(r0), "=r"(r1), "=r"(r2), "=r"(r3) : "r"(a));
}
__device__ __forceinline__ float2 lds_f2(uint32_t a) {
    float2 v; asm("ld.shared.v2.f32 {%0,%1}, [%2];" : "=f"(v.x), "=f"(v.y) : "r"(a));
    return v;
}
__device__ __forceinline__ void mma16816(float* c,
                                         uint32_t a0, uint32_t a1, uint32_t a2, uint32_t a3,
                                         uint32_t b0, uint32_t b1) {
    asm volatile("mma.sync.aligned.m16n8k16.row.col.f32.bf16.bf16.f32 "
                 "{%0,%1,%2,%3}, {%4,%5,%6,%7}, {%8,%9}, {%0,%1,%2,%3};"
                 : "+f"(c[0]), "+f"(c[1]), "+f"(c[2]), "+f"(c[3])
                 : "r"(a0), "r"(a1), "r"(a2), "r"(a3), "r"(b0), "r"(b1));
}
// Warp-private stage copy: warp's 16 W rows, k16 slice [k0, k0+16).
__device__ __forceinline__ void issue_stage_w(uint32_t buf, const float* wrow,
                                              int lane, int k0) {
#pragma unroll
    for (int i = 0; i < 2; i++) {
        int u = lane + 32 * i;
        int row = u >> 2, q = u & 3;
        const float* src = wrow + row * KTOT + k0 + 4 * q;
        uint32_t dst = buf + (uint32_t)(row * SROW + 4 * q) * 4u;
        asm volatile("cp.async.cg.shared.global [%0], [%1], 16;" :: "r"(dst), "l"(src));
    }
    asm volatile("cp.async.commit_group;" ::: "memory");
}

__global__ __launch_bounds__(512, 1)
void lc_conv_mma7(const float* __restrict__ x, const float* __restrict__ wgt,
                  const float* __restrict__ bias, float* __restrict__ out)
{
    extern __shared__ char smem[];
    const int t    = threadIdx.x;
    const int g    = t >> 8;          // position group 0/1
    const int tg   = t & 255;
    const int wg   = tg >> 5;         // warp in group 0..7
    const int m    = wg & 3;          // m-tile (16 output rows)
    const int kh   = wg >> 2;         // k-half
    const int lane = t & 31;
    const int gid  = lane >> 2, tig = lane & 3;

    const int bx = blockIdx.x, h = blockIdx.y;
    const int w0 = bx * 2;
    const int w  = w0 + g;

    __nv_bfloat16* xsg = (__nv_bfloat16*)(smem + g * XS_BYTES);
    const uint32_t ring = (uint32_t)__cvta_generic_to_shared(smem)
                        + 2u * XS_BYTES + (uint32_t)(g * 8 + wg) * RING_BYTES;

    // this warp's 16 weight rows for its position
    const float* wrow = wgt + ((size_t)(h * OW_ + w) * COUT_ + m * 16) * KTOT;

    // ---- prologue: issue stages 0..3 (land during X staging) ----
#pragma unroll
    for (int s = 0; s < 4; s++)
        issue_stage_w(ring + s * WSTG, wrow, lane, (2 * s + kh) * 16);

    // ---- X staging: 512 threads, 4-lane cooperative, hi/lo split ----
    {
        __nv_bfloat16* x0 = (__nv_bfloat16*)(smem);
        __nv_bfloat16* x1 = (__nv_bfloat16*)(smem + XS_BYTES);
        const int jj = t & 3;
        const int col = w0 - 1 + jj;
        const bool colok = (unsigned)col < IW_;
#pragma unroll 8
        for (int pass = 0; pass < 24; pass++) {
            int u  = pass * 128 + (t >> 2);
            int b  = u & 31;
            int ci = u >> 5;
            int c  = ci / 3, i = ci - 3 * c;
            int row = h + i - 1;
            float v = 0.f;
            if (colok && (unsigned)row < IH_)
                v = x[(((size_t)b * CIN_ + c) * IH_ + row) * IW_ + col];
            uint32_t ub = __float_as_uint(v);
            unsigned short hs = (unsigned short)(ub >> 16);
            float hf = __uint_as_float(ub & 0xFFFF0000u);
            __nv_bfloat16 lo = __float2bfloat16(v - hf);
            __nv_bfloat16 hi = reinterpret_cast<__nv_bfloat16&>(hs);
            int k = 3 * ci;
            if (jj < 3) {
                x0[(size_t)b * KROW + k + jj]        = hi;
                x0[(size_t)(b + 32) * KROW + k + jj] = lo;
            }
            if (jj >= 1) {
                x1[(size_t)b * KROW + k + jj - 1]        = hi;
                x1[(size_t)(b + 32) * KROW + k + jj - 1] = lo;
            }
        }
    }
    __syncthreads();    // X tiles visible; no more barriers until epilogue

    // ---- lane addressing ----
    uint32_t lds_b[4];
    {
        uint32_t base = (uint32_t)__cvta_generic_to_shared(xsg);
        int nrow = 8 * ((lane >> 4) & 1) + (lane & 7);
        int kadd = 8 * ((lane >> 3) & 1);
#pragma unroll
        for (int jp = 0; jp < 4; jp++)
            lds_b[jp] = base + (uint32_t)(16 * jp + nrow) * (KROW * 2) + kadd * 2;
    }
    const uint32_t a00o = (uint32_t)(gid * SROW + 2 * tig) * 4u;
    const uint32_t a10o = a00o + 8u * SROW * 4u;

    float acc1[8][4];   // Wh x n-tiles 0..7 (Xh | Xl)
    float acc2[4][4];   // Wl x n-tiles 0..3 (Xh)
#pragma unroll
    for (int j = 0; j < 8; j++)
#pragma unroll
        for (int q = 0; q < 4; q++) acc1[j][q] = 0.f;
#pragma unroll
    for (int j = 0; j < 4; j++)
#pragma unroll
        for (int q = 0; q < 4; q++) acc2[j][q] = 0.f;

    // ---- main loop: 9 k16 stages per warp, self-paced, no barriers ----
#pragma unroll 1
    for (int s = 0; s < NSTW; s++) {
        if (s + 4 < NSTW)
            issue_stage_w(ring + (uint32_t)((s + 4) % NBUF) * WSTG,
                          wrow, lane, (2 * (s + 4) + kh) * 16);
        // wait until stage s landed (issued_total = min(s+5,9); allow issued-(s+1) pending)
        if (s <= 4)      asm volatile("cp.async.wait_group 4;" ::: "memory");
        else if (s == 5) asm volatile("cp.async.wait_group 3;" ::: "memory");
        else if (s == 6) asm volatile("cp.async.wait_group 2;" ::: "memory");
        else if (s == 7) asm volatile("cp.async.wait_group 1;" ::: "memory");
        else             asm volatile("cp.async.wait_group 0;" ::: "memory");

        const uint32_t sA = ring + (uint32_t)(s % NBUF) * WSTG;

        // A fragments from private fp32 ring
        float2 f00 = lds_f2(sA + a00o);
        float2 f10 = lds_f2(sA + a10o);
        float2 f01 = lds_f2(sA + a00o + 32);
        float2 f11 = lds_f2(sA + a10o + 32);
        uint32_t ah0 = prmt_hi(__float_as_uint(f00.x), __float_as_uint(f00.y));
        uint32_t ah1 = prmt_hi(__float_as_uint(f10.x), __float_as_uint(f10.y));
        uint32_t ah2 = prmt_hi(__float_as_uint(f01.x), __float_as_uint(f01.y));
        uint32_t ah3 = prmt_hi(__float_as_uint(f11.x), __float_as_uint(f11.y));
        uint32_t al0 = lo_pack2(f00.x, f00.y);
        uint32_t al1 = lo_pack2(f10.x, f10.y);
        uint32_t al2 = lo_pack2(f01.x, f01.y);
        uint32_t al3 = lo_pack2(f11.x, f11.y);

        // B fragments at this warp's k offset
        uint32_t bb[16];
        uint32_t koff = (uint32_t)(2 * s + kh) * 32;
#pragma unroll
        for (int jp = 0; jp < 4; jp++)
            ldsm4(bb[4 * jp], bb[4 * jp + 1], bb[4 * jp + 2], bb[4 * jp + 3],
                  lds_b[jp] + koff);

#pragma unroll
        for (int j = 0; j < 8; j++) {
            uint32_t b0 = bb[(j >> 1) * 4 + (j & 1) * 2];
            uint32_t b1 = bb[(j >> 1) * 4 + (j & 1) * 2 + 1];
            mma16816(acc1[j], ah0, ah1, ah2, ah3, b0, b1);
        }
#pragma unroll
        for (int j = 0; j < 4; j++) {
            uint32_t b0 = bb[(j >> 1) * 4 + (j & 1) * 2];
            uint32_t b1 = bb[(j >> 1) * 4 + (j & 1) * 2 + 1];
            mma16816(acc2[j], al0, al1, al2, al3, b0, b1);
        }
    }

    // ---- split-K reduction: kh=1 writes partials over dead X tile, kh=0 adds ----
    __syncthreads();
    float* red = (float*)(smem + g * XS_BYTES) + m * (48 * 33);
    if (kh == 1) {
        int j = 0;
#pragma unroll
        for (int jj = 0; jj < 8; jj++)
#pragma unroll
            for (int q = 0; q < 4; q++) { red[j * 33 + lane] = acc1[jj][q]; j++; }
#pragma unroll
        for (int jj = 0; jj < 4; jj++)
#pragma unroll
            for (int q = 0; q < 4; q++) { red[j * 33 + lane] = acc2[jj][q]; j++; }
    }
    __syncthreads();

    if (kh == 0) {
        int j = 0;
#pragma unroll
        for (int jj = 0; jj < 8; jj++)
#pragma unroll
            for (int q = 0; q < 4; q++) { acc1[jj][q] += red[j * 33 + lane]; j++; }
#pragma unroll
        for (int jj = 0; jj < 4; jj++)
#pragma unroll
            for (int q = 0; q < 4; q++) { acc2[jj][q] += red[j * 33 + lane]; j++; }

        const int o_lo = m * 16 + gid;
        const int o_hi = o_lo + 8;
        const float bias_lo = bias[(o_lo * OH_ + h) * OW_ + w];
        const float bias_hi = bias[(o_hi * OH_ + h) * OW_ + w];
#pragma unroll
        for (int jj = 0; jj < 4; jj++) {
            int b = 8 * jj + 2 * tig;
            float v00 = acc1[jj][0] + acc1[jj + 4][0] + acc2[jj][0] + bias_lo;
            float v01 = acc1[jj][1] + acc1[jj + 4][1] + acc2[jj][1] + bias_lo;
            float v10 = acc1[jj][2] + acc1[jj + 4][2] + acc2[jj][2] + bias_hi;
            float v11 = acc1[jj][3] + acc1[jj + 4][3] + acc2[jj][3] + bias_hi;
            size_t p00 = (((size_t)b * COUT_ + o_lo) * OH_ + h) * OW_ + w;
            size_t p01 = (((size_t)(b + 1) * COUT_ + o_lo) * OH_ + h) * OW_ + w;
            out[p00] = v00;
            out[p01] = v01;
            out[p00 + (size_t)8 * OH_ * OW_] = v10;
            out[p01 + (size_t)8 * OH_ * OW_] = v11;
        }
    }
}

extern "C" void kernel_launch(void* const* d_in, const int* in_sizes, int n_in,
                              void* d_out, int out_size)
{
    const float* x    = (const float*)d_in[0];   // [32,32,64,64]
    const float* wgt  = (const float*)d_in[1];   // [64,64,64,32,3,3]
    const float* bias = (const float*)d_in[2];   // [64,64,64]
    float* out = (float*)d_out;                  // [32,64,64,64]

    cudaFuncSetAttribute(lc_conv_mma7, cudaFuncAttributeMaxDynamicSharedMemorySize, SMEM_DYN);
    dim3 grid(OW_ / 2, OH_);
    lc_conv_mma7<<<grid, 512, SMEM_DYN>>>(x, wgt, bias, out);
}